// round 14
// baseline (speedup 1.0000x reference)
#include <cuda_runtime.h>
#include <math.h>

#define NN 50000
#define EE 800000
#define D 96
#define HID 32
#define HEADS 3
#define FIN 16
#define F0 8
#define EDIM 4
// (1/sqrt(32)) * log2(e): fold softmax scale + exp->exp2 into Q at projection time
#define SC2L 0.25504070896656615f

// ---- scratch (static device globals; zero-initialized at module load) ----
__device__ float g_h0[NN * F0];
__device__ float g_h1[NN * D];
__device__ float g_Q[NN * D];            // pre-scaled by SC2L
__device__ float g_KV[NN * 2 * D];       // per-node interleaved: K[96] then V[96] (768B records)
__device__ float g_S[NN * D];
__device__ int   g_cnt[NN];              // zero at entry of every launch (self-restoring)
__device__ int   g_rowptr[NN + 1];
__device__ int   g_cur[NN];
__device__ int   g_psrc[EE];             // src index in CSR-permuted order
__device__ float4 g_pea[EE];             // edge_attr in CSR-permuted order
__device__ int   g_nodeperm[NN];         // nodes sorted by degree (counting sort)
__device__ int   g_dhist[256];           // degree histogram (self-restoring)
__device__ int   g_dcur[256];            // scanned degree-bin cursors
__device__ int   g_scan_ctr;             // last-block counter (self-restoring)
__device__ volatile int g_lb_status[64];
__device__ volatile int g_lb_agg[64];
__device__ volatile int g_lb_pref[64];

// ------- launch 0: layer-0 MLP + dst histogram + lookback-state zeroing -------
__global__ void k_l0_hist(const float* __restrict__ x, const float* __restrict__ W1,
                          const float* __restrict__ b1, const int* __restrict__ dst,
                          int n, int e) {
    int i = blockIdx.x * blockDim.x + threadIdx.x;
    if (i < 64) g_lb_status[i] = 0;
    if (i < e) atomicAdd(&g_cnt[dst[i]], 1);
    if (i >= n) return;
    float xr[FIN];
    const float4* xv = reinterpret_cast<const float4*>(x + i * FIN);
#pragma unroll
    for (int j = 0; j < 4; j++) {
        float4 t = xv[j];
        xr[j * 4 + 0] = t.x; xr[j * 4 + 1] = t.y; xr[j * 4 + 2] = t.z; xr[j * 4 + 3] = t.w;
    }
#pragma unroll
    for (int o = 0; o < F0; o++) {
        float acc = b1[o];
#pragma unroll
        for (int k = 0; k < FIN; k++) acc += xr[k] * W1[k * F0 + o];
        g_h0[i * F0 + o] = tanhf(acc);
    }
}

// ------- launch 1: scan (decoupled lookback) + degree hist + last-block bin scan -------
__global__ void k_scan_lb(int n, int etot) {
    __shared__ int sh[256];
    __shared__ int dh[256];
    __shared__ int sh_off;
    __shared__ int is_last;
    int b = blockIdx.x, t = threadIdx.x;
    int base = (b * 256 + t) * 4;
    int c[4];
    int local = 0;
    dh[t] = 0;
#pragma unroll
    for (int j = 0; j < 4; j++) {
        int i = base + j;
        c[j] = (i < n) ? g_cnt[i] : 0;
        if (i < n) g_cnt[i] = 0;
        local += c[j];
    }
    sh[t] = local;
    __syncthreads();
    for (int off = 1; off < 256; off <<= 1) {
        int u = (t >= off) ? sh[t - off] : 0;
        __syncthreads();
        sh[t] += u;
        __syncthreads();
    }
    int incl = sh[t];
    int agg = sh[255];
    if (t == 255) {
        g_lb_agg[b] = agg;
        __threadfence();
        g_lb_status[b] = (b == 0) ? 0 : 1;
    }
    __syncthreads();
    if (t == 0) {
        int excl = 0;
        for (int p = b - 1; p >= 0; --p) {
            int st;
            do { st = g_lb_status[p]; } while (st == 0);
            if (st == 2) { excl += g_lb_pref[p]; break; }
            excl += g_lb_agg[p];
        }
        sh_off = excl;
        g_lb_pref[b] = excl + agg;
        __threadfence();
        g_lb_status[b] = 2;
        if (b == 0) g_rowptr[n] = etot;
    }
    __syncthreads();
    int run = sh_off + incl - local;
#pragma unroll
    for (int j = 0; j < 4; j++) {
        int i = base + j;
        if (i < n) {
            g_rowptr[i] = run;
            g_cur[i] = run;
            run += c[j];
            atomicAdd(&dh[min(c[j], 255)], 1);
        }
    }
    __syncthreads();
    if (dh[t]) atomicAdd(&g_dhist[t], dh[t]);
    __threadfence();
    __syncthreads();
    if (t == 0) is_last = (atomicAdd(&g_scan_ctr, 1) == (int)gridDim.x - 1);
    __syncthreads();
    if (is_last) {
        if (t == 0) g_scan_ctr = 0;      // self-restore
        int v = g_dhist[t];
        g_dhist[t] = 0;                  // self-restore
        sh[t] = v;
        __syncthreads();
        for (int off = 1; off < 256; off <<= 1) {
            int u = (t >= off) ? sh[t - off] : 0;
            __syncthreads();
            sh[t] += u;
            __syncthreads();
        }
        g_dcur[t] = sh[t] - v;           // exclusive prefix
    }
}

// ------- proj body: 192 thr, 2 groups of 96, 16 nodes each; float4 LDS -------
template <int FI>
__device__ __forceinline__ void proj_body(
        const float* __restrict__ in, int node0,
        const float* __restrict__ Wq, const float* __restrict__ bq,
        const float* __restrict__ Wk, const float* __restrict__ bk,
        const float* __restrict__ Wv, const float* __restrict__ bv,
        const float* __restrict__ Ws, const float* __restrict__ bs,
        int n, float* shp) {
    const int NB = 32, NG = 16, F4 = FI / 4;
    int t = threadIdx.x;
    float4* sh4w = (float4*)shp;
    for (int idx = t; idx < NB * F4; idx += 192) {
        int j = idx / F4, kq = idx % F4;
        int nd = node0 + j;
        sh4w[idx] = (nd < n) ? *(const float4*)(in + nd * FI + 4 * kq)
                             : make_float4(0.f, 0.f, 0.f, 0.f);
    }
    __syncthreads();
    int grp = t / D;                 // 0 or 1
    int d = t - grp * D;
    int j0 = grp * NG;
    const float4* sh4 = (const float4*)shp;
    float aq[NG], ak[NG], av[NG], as_[NG];
    float vbq = bq[d], vbk = bk[d], vbv = bv[d], vbs = bs[d];
#pragma unroll
    for (int j = 0; j < NG; j++) { aq[j] = vbq; ak[j] = vbk; av[j] = vbv; as_[j] = vbs; }
    for (int k4 = 0; k4 < F4; k4++) {
        float wq[4], wk[4], wv[4], ws[4];
#pragma unroll
        for (int u = 0; u < 4; u++) {
            int k = 4 * k4 + u;
            wq[u] = Wq[k * D + d]; wk[u] = Wk[k * D + d];
            wv[u] = Wv[k * D + d]; ws[u] = Ws[k * D + d];
        }
#pragma unroll
        for (int j = 0; j < NG; j++) {
            float4 h = sh4[(j0 + j) * F4 + k4];
            aq[j] += h.x * wq[0] + h.y * wq[1] + h.z * wq[2] + h.w * wq[3];
            ak[j] += h.x * wk[0] + h.y * wk[1] + h.z * wk[2] + h.w * wk[3];
            av[j] += h.x * wv[0] + h.y * wv[1] + h.z * wv[2] + h.w * wv[3];
            as_[j] += h.x * ws[0] + h.y * ws[1] + h.z * ws[2] + h.w * ws[3];
        }
    }
#pragma unroll
    for (int j = 0; j < NG; j++) {
        int nd = node0 + j0 + j;
        if (nd < n) {
            g_Q[nd * D + d] = aq[j] * SC2L;
            g_KV[nd * 2 * D + d] = ak[j];
            g_KV[nd * 2 * D + D + d] = av[j];
            g_S[nd * D + d] = as_[j];
        }
    }
}

// ------- launch 2: fused edge scatter + layer-1 projection + node-perm scatter -------
__global__ void k_scatter_proj1(const int* __restrict__ src, const int* __restrict__ dst,
                                const float4* __restrict__ ea, int e, int scat_blocks,
                                int proj_blocks,
                                const float* __restrict__ Wq, const float* __restrict__ bq,
                                const float* __restrict__ Wk, const float* __restrict__ bk,
                                const float* __restrict__ Wv, const float* __restrict__ bv,
                                const float* __restrict__ Ws, const float* __restrict__ bs,
                                int n) {
    __shared__ float shp[32 * F0];
    int b = blockIdx.x;
    if (b < scat_blocks) {
        int i = b * 192 + threadIdx.x;
        if (i < e) {
            int d = dst[i];
            int pos = atomicAdd(&g_cur[d], 1);
            g_psrc[pos] = src[i];
            g_pea[pos] = ea[i];
        }
    } else if (b < scat_blocks + proj_blocks) {
        int node0 = (b - scat_blocks) * 32;
        proj_body<F0>(g_h0, node0, Wq, bq, Wk, bk, Wv, bv, Ws, bs, n, shp);
    } else {
        int i = (b - scat_blocks - proj_blocks) * 192 + threadIdx.x;
        if (i < n) {
            int deg = g_rowptr[i + 1] - g_rowptr[i];
            int pos = atomicAdd(&g_dcur[min(deg, 255)], 1);
            g_nodeperm[pos] = i;
        }
    }
}

// ------- launch 4: layer-2 projection -------
__global__ void k_proj2(const float* __restrict__ Wq, const float* __restrict__ bq,
                        const float* __restrict__ Wk, const float* __restrict__ bk,
                        const float* __restrict__ Wv, const float* __restrict__ bv,
                        const float* __restrict__ Ws, const float* __restrict__ bs,
                        int n) {
    __shared__ float shp[32 * D];
    int node0 = blockIdx.x * 32;
    proj_body<D>(g_h1, node0, Wq, bq, Wk, bk, Wv, bv, Ws, bs, n, shp);
}

__device__ __forceinline__ float dot4(float4 a, float4 b) {
    return a.x * b.x + a.y * b.y + a.z * b.z + a.w * b.w;
}

// ------- attention: 8 lanes/edge, 4 deg-sorted nodes/warp, DISTANCE-2 KV prefetch -------
// Two rotating KV register buffers; edge it+2's loads issue while edges it/it+1 compute,
// doubling outstanding loads per warp (the binding constraint per R11-R13 evidence).
__global__ void __launch_bounds__(128, 4) k_attn(const float* __restrict__ We, int out_sel,
                                                 float* __restrict__ out, int n, int e) {
    __shared__ float t_sh[16][12];   // per 8-lane group: t[c][jj] at [g][c*4+jj]
    int tid = threadIdx.x;
    int g = tid >> 3;                // group 0..15 within block
    int j = tid & 7;
    int slot = blockIdx.x * 16 + g;
    bool nvalid = slot < n;
    int node = nvalid ? g_nodeperm[slot] : 0;
    float* optr = (out_sel == 0) ? g_h1 : out;

    const float4* Q4 = (const float4*)g_Q;
    const float4* KV4 = (const float4*)g_KV;
    const float4* S4 = (const float4*)g_S;
    const float4* We4 = (const float4*)We;
    float4* O4 = (float4*)optr;

    float4 q0 = Q4[node * 24 + 0 * 8 + j];
    float4 q1 = Q4[node * 24 + 1 * 8 + j];
    float4 q2 = Q4[node * 24 + 2 * 8 + j];

    // t[c][jj] = q . We[jj] restricted to head c; store to shared (lanes j<4 write)
#pragma unroll
    for (int c = 0; c < HEADS; c++) {
        float4 qc = (c == 0) ? q0 : (c == 1) ? q1 : q2;
        float tv[EDIM];
#pragma unroll
        for (int jj = 0; jj < EDIM; jj++) {
            float p = dot4(qc, We4[jj * 24 + c * 8 + j]);
            p += __shfl_xor_sync(0xFFFFFFFFu, p, 1);
            p += __shfl_xor_sync(0xFFFFFFFFu, p, 2);
            p += __shfl_xor_sync(0xFFFFFFFFu, p, 4);
            tv[jj] = p;
        }
        if (j < 4) t_sh[g][c * 4 + j] = tv[j];
    }
    __syncwarp();

    int beg = nvalid ? g_rowptr[node] : 0;
    int end = nvalid ? g_rowptr[node + 1] : 0;
    int cnt = end - beg;
    int itmax = cnt;
    itmax = max(itmax, __shfl_xor_sync(0xFFFFFFFFu, itmax, 8));
    itmax = max(itmax, __shfl_xor_sync(0xFFFFFFFFu, itmax, 16));

    float4 acc0 = make_float4(0.f, 0.f, 0.f, 0.f);
    float4 acc1 = make_float4(0.f, 0.f, 0.f, 0.f);
    float4 acc2 = make_float4(0.f, 0.f, 0.f, 0.f);
    float s0 = 0.f, s1 = 0.f, s2 = 0.f;
    float r[HEADS][EDIM];
#pragma unroll
    for (int c = 0; c < HEADS; c++)
#pragma unroll
        for (int jj = 0; jj < EDIM; jj++) r[c][jj] = 0.f;

    // ---- prologue: KV of edges 0 and 1 into the two buffers ----
    float4 kkb[2][3], vvb[2][3];
#pragma unroll
    for (int st = 0; st < 2; st++) {
        int i0 = min(beg + st, e - 1);
        int base = g_psrc[i0] * 48;
#pragma unroll
        for (int f = 0; f < 3; f++) {
            kkb[st][f] = KV4[base + f * 8 + j];
            vvb[st][f] = KV4[base + 24 + f * 8 + j];
        }
    }

#pragma unroll 2
    for (int it = 0; it < itmax; it++) {
        int buf = it & 1;
        // take current edge's KV out of the buffer (register renames, no real moves
        // after unroll-2), then refill the slot with edge it+2's KV so its latency
        // spans two full iterations of compute.
        float4 kk0 = kkb[buf][0], kk1 = kkb[buf][1], kk2 = kkb[buf][2];
        float4 vv0 = vvb[buf][0], vv1 = vvb[buf][1], vv2 = vvb[buf][2];

        int inext = min(beg + it + 2, e - 1);
        int nbase = g_psrc[inext] * 48;
        kkb[buf][0] = KV4[nbase + 0 * 8 + j];
        kkb[buf][1] = KV4[nbase + 1 * 8 + j];
        kkb[buf][2] = KV4[nbase + 2 * 8 + j];
        vvb[buf][0] = KV4[nbase + 24 + 0 * 8 + j];
        vvb[buf][1] = KV4[nbase + 24 + 1 * 8 + j];
        vvb[buf][2] = KV4[nbase + 24 + 2 * 8 + j];

        float4 ea = g_pea[min(beg + it, e - 1)];   // sequential stream, L1-resident

        bool v = it < cnt;
        float p0 = dot4(q0, kk0);
        float p1 = dot4(q1, kk1);
        float p2 = dot4(q2, kk2);
        p0 += __shfl_xor_sync(0xFFFFFFFFu, p0, 1);
        p0 += __shfl_xor_sync(0xFFFFFFFFu, p0, 2);
        p0 += __shfl_xor_sync(0xFFFFFFFFu, p0, 4);
        p1 += __shfl_xor_sync(0xFFFFFFFFu, p1, 1);
        p1 += __shfl_xor_sync(0xFFFFFFFFu, p1, 2);
        p1 += __shfl_xor_sync(0xFFFFFFFFu, p1, 4);
        p2 += __shfl_xor_sync(0xFFFFFFFFu, p2, 1);
        p2 += __shfl_xor_sync(0xFFFFFFFFu, p2, 2);
        p2 += __shfl_xor_sync(0xFFFFFFFFu, p2, 4);

        float4 t0 = *(const float4*)&t_sh[g][0];
        float4 t1 = *(const float4*)&t_sh[g][4];
        float4 t2 = *(const float4*)&t_sh[g][8];
        float l0 = p0 + ea.x * t0.x + ea.y * t0.y + ea.z * t0.z + ea.w * t0.w;
        float l1 = p1 + ea.x * t1.x + ea.y * t1.y + ea.z * t1.z + ea.w * t1.w;
        float l2 = p2 + ea.x * t2.x + ea.y * t2.y + ea.z * t2.z + ea.w * t2.w;
        float e0 = v ? exp2f(l0) : 0.f;
        float e1 = v ? exp2f(l1) : 0.f;
        float e2 = v ? exp2f(l2) : 0.f;
        s0 += e0; s1 += e1; s2 += e2;
        r[0][0] += e0 * ea.x; r[0][1] += e0 * ea.y; r[0][2] += e0 * ea.z; r[0][3] += e0 * ea.w;
        r[1][0] += e1 * ea.x; r[1][1] += e1 * ea.y; r[1][2] += e1 * ea.z; r[1][3] += e1 * ea.w;
        r[2][0] += e2 * ea.x; r[2][1] += e2 * ea.y; r[2][2] += e2 * ea.z; r[2][3] += e2 * ea.w;
        acc0.x += e0 * vv0.x; acc0.y += e0 * vv0.y; acc0.z += e0 * vv0.z; acc0.w += e0 * vv0.w;
        acc1.x += e1 * vv1.x; acc1.y += e1 * vv1.y; acc1.z += e1 * vv1.z; acc1.w += e1 * vv1.w;
        acc2.x += e2 * vv2.x; acc2.y += e2 * vv2.y; acc2.z += e2 * vv2.z; acc2.w += e2 * vv2.w;
    }

    if (!nvalid) return;
    float inv0 = 1.0f / (s0 + 1e-16f);
    float inv1 = 1.0f / (s1 + 1e-16f);
    float inv2 = 1.0f / (s2 + 1e-16f);
#pragma unroll
    for (int c = 0; c < HEADS; c++) {
        int G = c * 8 + j;
        float4 a = (c == 0) ? acc0 : (c == 1) ? acc1 : acc2;
        float iv = (c == 0) ? inv0 : (c == 1) ? inv1 : inv2;
        float4 w0 = We4[0 * 24 + G];
        float4 w1 = We4[1 * 24 + G];
        float4 w2 = We4[2 * 24 + G];
        float4 w3 = We4[3 * 24 + G];
        float4 sk = S4[node * 24 + G];
        float4 o;
        o.x = (a.x + r[c][0] * w0.x + r[c][1] * w1.x + r[c][2] * w2.x + r[c][3] * w3.x) * iv + sk.x;
        o.y = (a.y + r[c][0] * w0.y + r[c][1] * w1.y + r[c][2] * w2.y + r[c][3] * w3.y) * iv + sk.y;
        o.z = (a.z + r[c][0] * w0.z + r[c][1] * w1.z + r[c][2] * w2.z + r[c][3] * w3.z) * iv + sk.z;
        o.w = (a.w + r[c][0] * w0.w + r[c][1] * w1.w + r[c][2] * w2.w + r[c][3] * w3.w) * iv + sk.w;
        o.x = tanhf(o.x); o.y = tanhf(o.y); o.z = tanhf(o.z); o.w = tanhf(o.w);
        O4[node * 24 + G] = o;
    }
}

// ---------------- launch ----------------
extern "C" void kernel_launch(void* const* d_in, const int* in_sizes, int n_in,
                              void* d_out, int out_size) {
    const float* x     = (const float*)d_in[0];
    const int*   eidx  = (const int*)d_in[1];
    const float* eattr = (const float*)d_in[2];
    const float* W1    = (const float*)d_in[3];
    const float* b1    = (const float*)d_in[4];
    const float* Wq1 = (const float*)d_in[5];  const float* bq1 = (const float*)d_in[6];
    const float* Wk1 = (const float*)d_in[7];  const float* bk1 = (const float*)d_in[8];
    const float* Wv1 = (const float*)d_in[9];  const float* bv1 = (const float*)d_in[10];
    const float* We1 = (const float*)d_in[11];
    const float* Ws1 = (const float*)d_in[12]; const float* bs1 = (const float*)d_in[13];
    const float* Wq2 = (const float*)d_in[14]; const float* bq2 = (const float*)d_in[15];
    const float* Wk2 = (const float*)d_in[16]; const float* bk2 = (const float*)d_in[17];
    const float* Wv2 = (const float*)d_in[18]; const float* bv2 = (const float*)d_in[19];
    const float* We2 = (const float*)d_in[20];
    const float* Ws2 = (const float*)d_in[21]; const float* bs2 = (const float*)d_in[22];

    int N = in_sizes[0] / FIN;
    int E = in_sizes[2] / EDIM;
    const int* src = eidx;
    const int* dst = eidx + E;
    float* out = (float*)d_out;

    int eb256 = (E + 255) / 256;
    int eb = (E + 191) / 192;       // scatter blocks (192 thr)
    int pb = (N + 31) / 32;         // proj blocks
    int nb = (N + 191) / 192;       // node-perm scatter blocks
    int ab = (N + 15) / 16;         // attn blocks (4 warps * 4 nodes)

    // 0: layer-0 MLP + histogram + lb-state zero
    k_l0_hist<<<eb256, 256>>>(x, W1, b1, dst, N, E);
    // 1: scan (restores g_cnt) + degree hist + last-block bin scan
    k_scan_lb<<<(N + 1023) / 1024, 256>>>(N, E);
    // 2: fused edge scatter + layer-1 projection + node-perm scatter
    k_scatter_proj1<<<eb + pb + nb, 192>>>(src, dst, (const float4*)eattr, E, eb, pb,
                                           Wq1, bq1, Wk1, bk1, Wv1, bv1, Ws1, bs1, N);
    // 3: attention layer 1  (ncu capture slot)
    k_attn<<<ab, 128>>>(We1, 0, out, N, E);
    // 4: layer-2 projection
    k_proj2<<<pb, 192>>>(Wq2, bq2, Wk2, bk2, Wv2, bv2, Ws2, bs2, N);
    // 5: attention layer 2
    k_attn<<<ab, 128>>>(We2, 1, out, N, E);
}

// round 15
// speedup vs baseline: 1.2801x; 1.2801x over previous
#include <cuda_runtime.h>
#include <math.h>

#define NN 50000
#define EE 800000
#define D 96
#define HID 32
#define HEADS 3
#define FIN 16
#define F0 8
#define EDIM 4
// (1/sqrt(32)) * log2(e): fold softmax scale + exp->exp2 into Q at projection time
#define SC2L 0.25504070896656615f

// ---- scratch (static device globals; zero-initialized at module load) ----
__device__ float g_h0[NN * F0];
__device__ float g_h1[NN * D];
__device__ float g_Q[NN * D];            // pre-scaled by SC2L
__device__ float g_KV[NN * 2 * D];       // per-node interleaved: K[96] then V[96] (768B records)
__device__ float g_S[NN * D];
__device__ int   g_cnt[NN];              // zero at entry of every launch (self-restoring)
__device__ int   g_rowptr[NN + 1];
__device__ int   g_cur[NN];
__device__ int   g_psrc[EE];             // src index in CSR-permuted order
__device__ float4 g_pea[EE];             // edge_attr in CSR-permuted order
__device__ int   g_nodeperm[NN];         // nodes sorted by degree (counting sort)
__device__ int   g_dhist[256];           // degree histogram (self-restoring)
__device__ int   g_dcur[256];            // scanned degree-bin cursors
__device__ int   g_scan_ctr;             // last-block counter (self-restoring)
__device__ volatile int g_lb_status[64];
__device__ volatile int g_lb_agg[64];
__device__ volatile int g_lb_pref[64];

// ---- f32x2 packed math (sm_100a; bit-identical IEEE fp32 per half) ----
__device__ __forceinline__ unsigned long long pack2(float lo, float hi) {
    unsigned long long r;
    asm("mov.b64 %0, {%1, %2};" : "=l"(r) : "f"(lo), "f"(hi));
    return r;
}
__device__ __forceinline__ unsigned long long fma2(unsigned long long a,
                                                   unsigned long long b,
                                                   unsigned long long c) {
    unsigned long long d_;
    asm("fma.rn.f32x2 %0, %1, %2, %3;" : "=l"(d_) : "l"(a), "l"(b), "l"(c));
    return d_;
}
__device__ __forceinline__ void unpack2(unsigned long long v, float& lo, float& hi) {
    asm("mov.b64 {%0, %1}, %2;" : "=f"(lo), "=f"(hi) : "l"(v));
}

// ------- launch 0: layer-0 MLP + dst histogram + lookback-state zeroing -------
__global__ void k_l0_hist(const float* __restrict__ x, const float* __restrict__ W1,
                          const float* __restrict__ b1, const int* __restrict__ dst,
                          int n, int e) {
    int i = blockIdx.x * blockDim.x + threadIdx.x;
    if (i < 64) g_lb_status[i] = 0;
    if (i < e) atomicAdd(&g_cnt[dst[i]], 1);
    if (i >= n) return;
    float xr[FIN];
    const float4* xv = reinterpret_cast<const float4*>(x + i * FIN);
#pragma unroll
    for (int j = 0; j < 4; j++) {
        float4 t = xv[j];
        xr[j * 4 + 0] = t.x; xr[j * 4 + 1] = t.y; xr[j * 4 + 2] = t.z; xr[j * 4 + 3] = t.w;
    }
#pragma unroll
    for (int o = 0; o < F0; o++) {
        float acc = b1[o];
#pragma unroll
        for (int k = 0; k < FIN; k++) acc += xr[k] * W1[k * F0 + o];
        g_h0[i * F0 + o] = tanhf(acc);
    }
}

// ------- launch 1: scan (decoupled lookback) + degree hist + last-block bin scan -------
__global__ void k_scan_lb(int n, int etot) {
    __shared__ int sh[256];
    __shared__ int dh[256];
    __shared__ int sh_off;
    __shared__ int is_last;
    int b = blockIdx.x, t = threadIdx.x;
    int base = (b * 256 + t) * 4;
    int c[4];
    int local = 0;
    dh[t] = 0;
#pragma unroll
    for (int j = 0; j < 4; j++) {
        int i = base + j;
        c[j] = (i < n) ? g_cnt[i] : 0;
        if (i < n) g_cnt[i] = 0;
        local += c[j];
    }
    sh[t] = local;
    __syncthreads();
    for (int off = 1; off < 256; off <<= 1) {
        int u = (t >= off) ? sh[t - off] : 0;
        __syncthreads();
        sh[t] += u;
        __syncthreads();
    }
    int incl = sh[t];
    int agg = sh[255];
    if (t == 255) {
        g_lb_agg[b] = agg;
        __threadfence();
        g_lb_status[b] = (b == 0) ? 0 : 1;
    }
    __syncthreads();
    if (t == 0) {
        int excl = 0;
        for (int p = b - 1; p >= 0; --p) {
            int st;
            do { st = g_lb_status[p]; } while (st == 0);
            if (st == 2) { excl += g_lb_pref[p]; break; }
            excl += g_lb_agg[p];
        }
        sh_off = excl;
        g_lb_pref[b] = excl + agg;
        __threadfence();
        g_lb_status[b] = 2;
        if (b == 0) g_rowptr[n] = etot;
    }
    __syncthreads();
    int run = sh_off + incl - local;
#pragma unroll
    for (int j = 0; j < 4; j++) {
        int i = base + j;
        if (i < n) {
            g_rowptr[i] = run;
            g_cur[i] = run;
            run += c[j];
            atomicAdd(&dh[min(c[j], 255)], 1);
        }
    }
    __syncthreads();
    if (dh[t]) atomicAdd(&g_dhist[t], dh[t]);
    __threadfence();
    __syncthreads();
    if (t == 0) is_last = (atomicAdd(&g_scan_ctr, 1) == (int)gridDim.x - 1);
    __syncthreads();
    if (is_last) {
        if (t == 0) g_scan_ctr = 0;      // self-restore
        int v = g_dhist[t];
        g_dhist[t] = 0;                  // self-restore
        sh[t] = v;
        __syncthreads();
        for (int off = 1; off < 256; off <<= 1) {
            int u = (t >= off) ? sh[t - off] : 0;
            __syncthreads();
            sh[t] += u;
            __syncthreads();
        }
        g_dcur[t] = sh[t] - v;           // exclusive prefix
    }
}

// ------- proj body (f32x2): 192 thr, 2 groups of 96, 8 node-PAIRS each -------
// Transposed smem tile sh[k][node] (pitch 34 words: 8B-aligned b64 node-pair reads,
// bank-spread fill). Inner loop: packed fma.rn.f32x2 -> 2 FMAs/instruction.
template <int FI>
__device__ __forceinline__ void proj_body(
        const float* __restrict__ in, int node0,
        const float* __restrict__ Wq, const float* __restrict__ bq,
        const float* __restrict__ Wk, const float* __restrict__ bk,
        const float* __restrict__ Wv, const float* __restrict__ bv,
        const float* __restrict__ Ws, const float* __restrict__ bs,
        int n, float* shp) {
    const int NB = 32, NG = 16, F4 = FI / 4, PITCH = NB + 2;
    int t = threadIdx.x;
    float (*sh)[PITCH] = (float (*)[PITCH])shp;
    for (int idx = t; idx < NB * F4; idx += 192) {
        int j = idx / F4, k4 = idx % F4;
        int nd = node0 + j;
        float4 h = (nd < n) ? *(const float4*)(in + nd * FI + 4 * k4)
                            : make_float4(0.f, 0.f, 0.f, 0.f);
        sh[4 * k4 + 0][j] = h.x;
        sh[4 * k4 + 1][j] = h.y;
        sh[4 * k4 + 2][j] = h.z;
        sh[4 * k4 + 3][j] = h.w;
    }
    __syncthreads();
    int grp = t / D;                 // 0 or 1
    int d = t - grp * D;
    int j0 = grp * NG;

    unsigned long long aq[8], ak[8], av[8], as_[8];
    unsigned long long bq2 = pack2(bq[d], bq[d]);
    unsigned long long bk2 = pack2(bk[d], bk[d]);
    unsigned long long bv2 = pack2(bv[d], bv[d]);
    unsigned long long bs2 = pack2(bs[d], bs[d]);
#pragma unroll
    for (int p = 0; p < 8; p++) { aq[p] = bq2; ak[p] = bk2; av[p] = bv2; as_[p] = bs2; }

    for (int k = 0; k < FI; k++) {
        float wq = Wq[k * D + d], wk = Wk[k * D + d];
        float wv = Wv[k * D + d], ws = Ws[k * D + d];
        unsigned long long wq2 = pack2(wq, wq);
        unsigned long long wk2 = pack2(wk, wk);
        unsigned long long wv2 = pack2(wv, wv);
        unsigned long long ws2 = pack2(ws, ws);
#pragma unroll
        for (int p = 0; p < 8; p++) {
            unsigned long long h2 = *(const unsigned long long*)&sh[k][j0 + 2 * p];
            aq[p] = fma2(h2, wq2, aq[p]);
            ak[p] = fma2(h2, wk2, ak[p]);
            av[p] = fma2(h2, wv2, av[p]);
            as_[p] = fma2(h2, ws2, as_[p]);
        }
    }

#pragma unroll
    for (int p = 0; p < 8; p++) {
        float q0, q1, k0, k1, v0, v1, s0, s1;
        unpack2(aq[p], q0, q1);
        unpack2(ak[p], k0, k1);
        unpack2(av[p], v0, v1);
        unpack2(as_[p], s0, s1);
        int nd = node0 + j0 + 2 * p;
        if (nd < n) {
            g_Q[nd * D + d] = q0 * SC2L;
            g_KV[nd * 2 * D + d] = k0;
            g_KV[nd * 2 * D + D + d] = v0;
            g_S[nd * D + d] = s0;
        }
        if (nd + 1 < n) {
            g_Q[(nd + 1) * D + d] = q1 * SC2L;
            g_KV[(nd + 1) * 2 * D + d] = k1;
            g_KV[(nd + 1) * 2 * D + D + d] = v1;
            g_S[(nd + 1) * D + d] = s1;
        }
    }
}

// ------- launch 2: fused edge scatter + layer-1 projection + node-perm scatter -------
__global__ void k_scatter_proj1(const int* __restrict__ src, const int* __restrict__ dst,
                                const float4* __restrict__ ea, int e, int scat_blocks,
                                int proj_blocks,
                                const float* __restrict__ Wq, const float* __restrict__ bq,
                                const float* __restrict__ Wk, const float* __restrict__ bk,
                                const float* __restrict__ Wv, const float* __restrict__ bv,
                                const float* __restrict__ Ws, const float* __restrict__ bs,
                                int n) {
    __shared__ float shp[F0 * 34];
    int b = blockIdx.x;
    if (b < scat_blocks) {
        int i = b * 192 + threadIdx.x;
        if (i < e) {
            int d = dst[i];
            int pos = atomicAdd(&g_cur[d], 1);
            g_psrc[pos] = src[i];
            g_pea[pos] = ea[i];
        }
    } else if (b < scat_blocks + proj_blocks) {
        int node0 = (b - scat_blocks) * 32;
        proj_body<F0>(g_h0, node0, Wq, bq, Wk, bk, Wv, bv, Ws, bs, n, shp);
    } else {
        int i = (b - scat_blocks - proj_blocks) * 192 + threadIdx.x;
        if (i < n) {
            int deg = g_rowptr[i + 1] - g_rowptr[i];
            int pos = atomicAdd(&g_dcur[min(deg, 255)], 1);
            g_nodeperm[pos] = i;
        }
    }
}

// ------- launch 4: layer-2 projection -------
__global__ void k_proj2(const float* __restrict__ Wq, const float* __restrict__ bq,
                        const float* __restrict__ Wk, const float* __restrict__ bk,
                        const float* __restrict__ Wv, const float* __restrict__ bv,
                        const float* __restrict__ Ws, const float* __restrict__ bs,
                        int n) {
    __shared__ float shp[D * 34];
    int node0 = blockIdx.x * 32;
    proj_body<D>(g_h1, node0, Wq, bq, Wk, bk, Wv, bv, Ws, bs, n, shp);
}

__device__ __forceinline__ float dot4(float4 a, float4 b) {
    return a.x * b.x + a.y * b.y + a.z * b.z + a.w * b.w;
}

// ------- attention: R11 config (best measured). 8 lanes/edge, 4 deg-sorted nodes/warp,
// 256-thr blocks, 2 blk/SM, distance-1 software pipeline. -------
__global__ void __launch_bounds__(256, 2) k_attn(const float* __restrict__ We, int out_sel,
                                                 float* __restrict__ out, int n, int e) {
    int warp = (blockIdx.x * blockDim.x + threadIdx.x) >> 5;
    int lane = threadIdx.x & 31;
    int j = lane & 7;
    int slot = warp * 4 + (lane >> 3);
    bool nvalid = slot < n;
    int node = nvalid ? g_nodeperm[slot] : 0;
    float* optr = (out_sel == 0) ? g_h1 : out;

    const float4* Q4 = (const float4*)g_Q;
    const float4* KV4 = (const float4*)g_KV;
    const float4* S4 = (const float4*)g_S;
    const float4* We4 = (const float4*)We;
    float4* O4 = (float4*)optr;

    float4 q0 = Q4[node * 24 + 0 * 8 + j];
    float4 q1 = Q4[node * 24 + 1 * 8 + j];
    float4 q2 = Q4[node * 24 + 2 * 8 + j];

    // t[c][jj] = q . We[jj] restricted to head c (reduced over the 8 sublanes)
    float t[HEADS][EDIM];
#pragma unroll
    for (int c = 0; c < HEADS; c++) {
        float4 qc = (c == 0) ? q0 : (c == 1) ? q1 : q2;
#pragma unroll
        for (int jj = 0; jj < EDIM; jj++) {
            float p = dot4(qc, We4[jj * 24 + c * 8 + j]);
            p += __shfl_xor_sync(0xFFFFFFFFu, p, 1);
            p += __shfl_xor_sync(0xFFFFFFFFu, p, 2);
            p += __shfl_xor_sync(0xFFFFFFFFu, p, 4);
            t[c][jj] = p;
        }
    }

    int beg = nvalid ? g_rowptr[node] : 0;
    int end = nvalid ? g_rowptr[node + 1] : 0;
    int cnt = end - beg;
    int itmax = cnt;
    itmax = max(itmax, __shfl_xor_sync(0xFFFFFFFFu, itmax, 8));
    itmax = max(itmax, __shfl_xor_sync(0xFFFFFFFFu, itmax, 16));

    float4 acc0 = make_float4(0.f, 0.f, 0.f, 0.f);
    float4 acc1 = make_float4(0.f, 0.f, 0.f, 0.f);
    float4 acc2 = make_float4(0.f, 0.f, 0.f, 0.f);
    float s0 = 0.f, s1 = 0.f, s2 = 0.f;
    float r[HEADS][EDIM];
#pragma unroll
    for (int c = 0; c < HEADS; c++)
#pragma unroll
        for (int jj = 0; jj < EDIM; jj++) r[c][jj] = 0.f;

    // ---- prologue: load edge 0 ----
    float4 ea, kk0, kk1, kk2, vv0, vv1, vv2;
    {
        int i0 = min(beg, e - 1);
        int sidx = g_psrc[i0];
        ea = g_pea[i0];
        int base = sidx * 48;
        kk0 = KV4[base + 0 * 8 + j];
        kk1 = KV4[base + 1 * 8 + j];
        kk2 = KV4[base + 2 * 8 + j];
        vv0 = KV4[base + 24 + 0 * 8 + j];
        vv1 = KV4[base + 24 + 1 * 8 + j];
        vv2 = KV4[base + 24 + 2 * 8 + j];
    }

#pragma unroll 1
    for (int it = 0; it < itmax; it++) {
        // prefetch edge it+1 (clamped) before the dependency chain
        int inext = min(beg + it + 1, e - 1);
        int nsidx = g_psrc[inext];
        float4 nea = g_pea[inext];
        int nbase = nsidx * 48;
        float4 nkk0 = KV4[nbase + 0 * 8 + j];
        float4 nkk1 = KV4[nbase + 1 * 8 + j];
        float4 nkk2 = KV4[nbase + 2 * 8 + j];
        float4 nvv0 = KV4[nbase + 24 + 0 * 8 + j];
        float4 nvv1 = KV4[nbase + 24 + 1 * 8 + j];
        float4 nvv2 = KV4[nbase + 24 + 2 * 8 + j];

        bool v = it < cnt;
        float p0 = dot4(q0, kk0);
        float p1 = dot4(q1, kk1);
        float p2 = dot4(q2, kk2);
        p0 += __shfl_xor_sync(0xFFFFFFFFu, p0, 1);
        p0 += __shfl_xor_sync(0xFFFFFFFFu, p0, 2);
        p0 += __shfl_xor_sync(0xFFFFFFFFu, p0, 4);
        p1 += __shfl_xor_sync(0xFFFFFFFFu, p1, 1);
        p1 += __shfl_xor_sync(0xFFFFFFFFu, p1, 2);
        p1 += __shfl_xor_sync(0xFFFFFFFFu, p1, 4);
        p2 += __shfl_xor_sync(0xFFFFFFFFu, p2, 1);
        p2 += __shfl_xor_sync(0xFFFFFFFFu, p2, 2);
        p2 += __shfl_xor_sync(0xFFFFFFFFu, p2, 4);

        float l0 = p0 + ea.x * t[0][0] + ea.y * t[0][1] + ea.z * t[0][2] + ea.w * t[0][3];
        float l1 = p1 + ea.x * t[1][0] + ea.y * t[1][1] + ea.z * t[1][2] + ea.w * t[1][3];
        float l2 = p2 + ea.x * t[2][0] + ea.y * t[2][1] + ea.z * t[2][2] + ea.w * t[2][3];
        float e0 = v ? exp2f(l0) : 0.f;
        float e1 = v ? exp2f(l1) : 0.f;
        float e2 = v ? exp2f(l2) : 0.f;
        s0 += e0; s1 += e1; s2 += e2;
        r[0][0] += e0 * ea.x; r[0][1] += e0 * ea.y; r[0][2] += e0 * ea.z; r[0][3] += e0 * ea.w;
        r[1][0] += e1 * ea.x; r[1][1] += e1 * ea.y; r[1][2] += e1 * ea.z; r[1][3] += e1 * ea.w;
        r[2][0] += e2 * ea.x; r[2][1] += e2 * ea.y; r[2][2] += e2 * ea.z; r[2][3] += e2 * ea.w;
        acc0.x += e0 * vv0.x; acc0.y += e0 * vv0.y; acc0.z += e0 * vv0.z; acc0.w += e0 * vv0.w;
        acc1.x += e1 * vv1.x; acc1.y += e1 * vv1.y; acc1.z += e1 * vv1.z; acc1.w += e1 * vv1.w;
        acc2.x += e2 * vv2.x; acc2.y += e2 * vv2.y; acc2.z += e2 * vv2.z; acc2.w += e2 * vv2.w;

        // rotate pipeline
        ea = nea;
        kk0 = nkk0; kk1 = nkk1; kk2 = nkk2;
        vv0 = nvv0; vv1 = nvv1; vv2 = nvv2;
    }

    if (!nvalid) return;
    float inv0 = 1.0f / (s0 + 1e-16f);
    float inv1 = 1.0f / (s1 + 1e-16f);
    float inv2 = 1.0f / (s2 + 1e-16f);
#pragma unroll
    for (int c = 0; c < HEADS; c++) {
        int G = c * 8 + j;
        float4 a = (c == 0) ? acc0 : (c == 1) ? acc1 : acc2;
        float iv = (c == 0) ? inv0 : (c == 1) ? inv1 : inv2;
        float4 w0 = We4[0 * 24 + G];
        float4 w1 = We4[1 * 24 + G];
        float4 w2 = We4[2 * 24 + G];
        float4 w3 = We4[3 * 24 + G];
        float4 sk = S4[node * 24 + G];
        float4 o;
        o.x = (a.x + r[c][0] * w0.x + r[c][1] * w1.x + r[c][2] * w2.x + r[c][3] * w3.x) * iv + sk.x;
        o.y = (a.y + r[c][0] * w0.y + r[c][1] * w1.y + r[c][2] * w2.y + r[c][3] * w3.y) * iv + sk.y;
        o.z = (a.z + r[c][0] * w0.z + r[c][1] * w1.z + r[c][2] * w2.z + r[c][3] * w3.z) * iv + sk.z;
        o.w = (a.w + r[c][0] * w0.w + r[c][1] * w1.w + r[c][2] * w2.w + r[c][3] * w3.w) * iv + sk.w;
        o.x = tanhf(o.x); o.y = tanhf(o.y); o.z = tanhf(o.z); o.w = tanhf(o.w);
        O4[node * 24 + G] = o;
    }
}

// ---------------- launch ----------------
extern "C" void kernel_launch(void* const* d_in, const int* in_sizes, int n_in,
                              void* d_out, int out_size) {
    const float* x     = (const float*)d_in[0];
    const int*   eidx  = (const int*)d_in[1];
    const float* eattr = (const float*)d_in[2];
    const float* W1    = (const float*)d_in[3];
    const float* b1    = (const float*)d_in[4];
    const float* Wq1 = (const float*)d_in[5];  const float* bq1 = (const float*)d_in[6];
    const float* Wk1 = (const float*)d_in[7];  const float* bk1 = (const float*)d_in[8];
    const float* Wv1 = (const float*)d_in[9];  const float* bv1 = (const float*)d_in[10];
    const float* We1 = (const float*)d_in[11];
    const float* Ws1 = (const float*)d_in[12]; const float* bs1 = (const float*)d_in[13];
    const float* Wq2 = (const float*)d_in[14]; const float* bq2 = (const float*)d_in[15];
    const float* Wk2 = (const float*)d_in[16]; const float* bk2 = (const float*)d_in[17];
    const float* Wv2 = (const float*)d_in[18]; const float* bv2 = (const float*)d_in[19];
    const float* We2 = (const float*)d_in[20];
    const float* Ws2 = (const float*)d_in[21]; const float* bs2 = (const float*)d_in[22];

    int N = in_sizes[0] / FIN;
    int E = in_sizes[2] / EDIM;
    const int* src = eidx;
    const int* dst = eidx + E;
    float* out = (float*)d_out;

    int eb256 = (E + 255) / 256;
    int eb = (E + 191) / 192;       // scatter blocks (192 thr)
    int pb = (N + 31) / 32;         // proj blocks
    int nb = (N + 191) / 192;       // node-perm scatter blocks
    int ab = (N + 31) / 32;         // attn blocks (8 warps * 4 nodes)

    // 0: layer-0 MLP + histogram + lb-state zero
    k_l0_hist<<<eb256, 256>>>(x, W1, b1, dst, N, E);
    // 1: scan (restores g_cnt) + degree hist + last-block bin scan
    k_scan_lb<<<(N + 1023) / 1024, 256>>>(N, E);
    // 2: fused edge scatter + layer-1 projection + node-perm scatter
    k_scatter_proj1<<<eb + pb + nb, 192>>>(src, dst, (const float4*)eattr, E, eb, pb,
                                           Wq1, bq1, Wk1, bk1, Wv1, bv1, Ws1, bs1, N);
    // 3: attention layer 1  (ncu capture slot)
    k_attn<<<ab, 256>>>(We1, 0, out, N, E);
    // 4: layer-2 projection (f32x2 packed FMA)
    k_proj2<<<pb, 192>>>(Wq2, bq2, Wk2, bk2, Wv2, bv2, Ws2, bs2, N);
    // 5: attention layer 2
    k_attn<<<ab, 256>>>(We2, 1, out, N, E);
}